// round 17
// baseline (speedup 1.0000x reference)
#include <cuda_runtime.h>
#include <cuda_fp16.h>

// Problem constants
#define BATCH 32
#define CIN   256
#define COUT  256
#define NEXP  8
#define CHID  64
#define HW    3136   // 56*56

// GEMM tiling: CTA 128 x 112, 8 warps (4m x 2n), warp tile 32 x 56
#define BM 128
#define BK 64             // 4 k-steps of 16
#define NCHUNKS (CIN / BK)   // 4
#define NSTAGES 3

// per-stage smem bytes: A = 8 mt * 4 ks * 32 lane * 16B = 16384; B = 64 * 240 = 15360
#define A_BYTES 16384
#define STG_BYTES 31744
#define SM_BYTES (NSTAGES * STG_BYTES)   // 95232

// Device scratch (allocation-free per harness rules)
__device__ float g_pooled[BATCH * CIN];
// A (w_dyn) fp16 in m16n8k16 A-fragment layout: [b][mt 16][kstep 16][lane 32][8 halves]
__device__ __half g_wh[BATCH * 16 * 16 * 32 * 8];        // 4 MB
// fp16 copy of x
__device__ __half g_xh[(size_t)BATCH * CIN * HW];        // 52 MB

__device__ __forceinline__ unsigned smem_u32(const void* p) {
    unsigned a;
    asm("{ .reg .u64 t; cvta.to.shared.u64 t, %1; cvt.u32.u64 %0, t; }" : "=r"(a) : "l"(p));
    return a;
}
__device__ __forceinline__ void cp_async16(unsigned dst, const void* src) {
    asm volatile("cp.async.cg.shared.global [%0], [%1], 16;" :: "r"(dst), "l"(src) : "memory");
}
#define CP_COMMIT() asm volatile("cp.async.commit_group;" ::: "memory")
#define CP_WAIT1()  asm volatile("cp.async.wait_group 1;" ::: "memory")
#define CP_WAIT0()  asm volatile("cp.async.wait_group 0;" ::: "memory")

__device__ __forceinline__ void lds128(unsigned* r, unsigned addr) {
    asm volatile("ld.shared.v4.b32 {%0,%1,%2,%3}, [%4];"
                 : "=r"(r[0]), "=r"(r[1]), "=r"(r[2]), "=r"(r[3]) : "r"(addr));
}
__device__ __forceinline__ void ldmx2t(unsigned& b0, unsigned& b1, unsigned addr) {
    asm volatile("ldmatrix.sync.aligned.m8n8.x2.trans.shared.b16 {%0,%1}, [%2];"
                 : "=r"(b0), "=r"(b1) : "r"(addr));
}
__device__ __forceinline__ void ldmx4t(unsigned& b0, unsigned& b1, unsigned& b2, unsigned& b3,
                                       unsigned addr) {
    asm volatile("ldmatrix.sync.aligned.m8n8.x4.trans.shared.b16 {%0,%1,%2,%3}, [%4];"
                 : "=r"(b0), "=r"(b1), "=r"(b2), "=r"(b3) : "r"(addr));
}
__device__ __forceinline__ void mma16(float4& d, const unsigned* a, unsigned b0, unsigned b1) {
    asm volatile(
        "mma.sync.aligned.m16n8k16.row.col.f32.f16.f16.f32 "
        "{%0,%1,%2,%3}, {%4,%5,%6,%7}, {%8,%9}, {%0,%1,%2,%3};"
        : "+f"(d.x), "+f"(d.y), "+f"(d.z), "+f"(d.w)
        : "r"(a[0]), "r"(a[1]), "r"(a[2]), "r"(a[3]), "r"(b0), "r"(b1));
}

// ---------------------------------------------------------------------------
// Kernel 1: global average pool + fp16 copy of x
// ---------------------------------------------------------------------------
__global__ void pool_kernel(const float* __restrict__ x) {
    const int bc = blockIdx.x;
    const float* __restrict__ p = x + (size_t)bc * HW;
    __half2* __restrict__ q2 = (__half2*)(g_xh + (size_t)bc * HW);
    const int tid = threadIdx.x;

    float s = 0.0f;
    const float4* p4 = (const float4*)p;
    for (int i = tid; i < HW / 4; i += 256) {
        float4 v = p4[i];
        s += v.x + v.y + v.z + v.w;
        __half2 h2[2];
        h2[0] = __floats2half2_rn(v.x, v.y);
        h2[1] = __floats2half2_rn(v.z, v.w);
        *(uint2*)(q2 + i * 2) = *(uint2*)h2;
    }
    for (int off = 16; off > 0; off >>= 1)
        s += __shfl_xor_sync(0xFFFFFFFFu, s, off);

    __shared__ float red[8];
    if ((tid & 31) == 0) red[tid >> 5] = s;
    __syncthreads();
    if (tid == 0) {
        float t = 0.0f;
        #pragma unroll
        for (int w = 0; w < 8; w++) t += red[w];
        g_pooled[bc] = t * (1.0f / (float)HW);
    }
}

// ---------------------------------------------------------------------------
// Kernel 2 (FUSED): MLP + softmax + w_dyn -> fp16 fragment layout.
// Grid (16 mt, 8 bgroups) x 512.  Each block recomputes attn for its 4 b's
// (cheap: ~68K FMA), then writes its w_dyn fragment slice, coalesced STG.128.
// ---------------------------------------------------------------------------
__global__ __launch_bounds__(512)
void attn_wdyn_kernel(const float* __restrict__ w1,
                      const float* __restrict__ b1,
                      const float* __restrict__ w2,
                      const float* __restrict__ b2,
                      const float* __restrict__ weights) {
    const int mt = blockIdx.x;
    const int b0 = blockIdx.y * 4;
    const int t  = threadIdx.x;

    __shared__ float sp[4][CIN];
    __shared__ float sh[4][CHID];
    __shared__ float sa[4][NEXP];

    for (int i = t; i < 4 * CIN; i += 512)
        sp[i >> 8][i & 255] = g_pooled[b0 * CIN + i];
    __syncthreads();

    // hidden layer: 4 b x 64 o x 2 halves
    {
        const int bb = t >> 7;            // 0..3
        const int o  = (t >> 1) & 63;
        const int q  = t & 1;
        float p = 0.0f;
        const float* w1r = w1 + o * CIN + q * 128;
        const float* spq = sp[bb] + q * 128;
        #pragma unroll 16
        for (int j = 0; j < 128; j++) p = fmaf(w1r[j], spq[j], p);
        p += __shfl_xor_sync(0xFFFFFFFFu, p, 1);
        if (q == 0) sh[bb][o] = fmaxf(p + b1[o], 0.0f);
    }
    __syncthreads();

    if (t < 32) {
        const int bb = t >> 3, e = t & 7;
        float l = b2[e];
        const float* w2r = w2 + e * CHID;
        #pragma unroll
        for (int j = 0; j < CHID; j++) l = fmaf(w2r[j], sh[bb][j], l);
        sa[bb][e] = l;
    }
    __syncthreads();

    if (t < 4) {
        float m = sa[t][0];
        #pragma unroll
        for (int e = 1; e < NEXP; e++) m = fmaxf(m, sa[t][e]);
        float sum = 0.0f;
        float ex[NEXP];
        #pragma unroll
        for (int e = 0; e < NEXP; e++) { ex[e] = __expf(sa[t][e] - m); sum += ex[e]; }
        float inv = 1.0f / sum;
        #pragma unroll
        for (int e = 0; e < NEXP; e++) sa[t][e] = ex[e] * inv;
    }
    __syncthreads();

    // ---- w_dyn fragment write (same mapping as before) ----
    const int kstep = t >> 5;
    const int lane  = t & 31;

    float w[8][NEXP];
    #pragma unroll
    for (int hp = 0; hp < 4; hp++) {
        const int r8 = hp & 1;
        const int k8 = hp >> 1;
        const int co = mt * 16 + r8 * 8 + (lane >> 2);
        const int ci = kstep * 16 + k8 * 8 + (lane & 3) * 2;
        #pragma unroll
        for (int e = 0; e < NEXP; e++) {
            const float2 v = *(const float2*)(weights + ((size_t)e * COUT + co) * CIN + ci);
            w[2 * hp][e] = v.x;
            w[2 * hp + 1][e] = v.y;
        }
    }

    #pragma unroll
    for (int bb = 0; bb < 4; bb++) {
        const int b = b0 + bb;
        float av[NEXP];
        #pragma unroll
        for (int e = 0; e < NEXP; e++) av[e] = sa[bb][e];
        __half2 h2[4];
        #pragma unroll
        for (int hp = 0; hp < 4; hp++) {
            float s0 = 0.0f, s1 = 0.0f;
            #pragma unroll
            for (int e = 0; e < NEXP; e++) {
                s0 = fmaf(av[e], w[2 * hp][e], s0);
                s1 = fmaf(av[e], w[2 * hp + 1][e], s1);
            }
            h2[hp] = __floats2half2_rn(s0, s1);
        }
        const size_t unit = (((size_t)b * 16 + mt) * 16 + kstep) * 32 + lane;
        *(uint4*)(g_wh + unit * 8) = *(uint4*)h2;
    }
}

// ---------------------------------------------------------------------------
// Kernel 3: fp16 m16n8k16 batched GEMM (BK=64: half the chunk boundaries)
//   out[b] (256 x 3136) = w_dyn[b] @ x[b]
//   CTA 128 x 112; 8 warps (4m x 2n); warp tile 32 x 56; 3-stage ring,
//   2 chunks (of 64 k) in flight.
// ---------------------------------------------------------------------------
__global__ __launch_bounds__(256, 2)
void gemm_mma(float* __restrict__ out) {
    extern __shared__ char smc[];
    const unsigned sbase = smem_u32(smc);

    const int tid  = threadIdx.x;
    const int wid  = tid >> 5;
    const int lane = tid & 31;
    const int wm = wid >> 1;          // 0..3  (m offset 32*wm)
    const int wn = wid & 1;           // 0..1  (n offset 56*wn)

    const int n0 = blockIdx.x * 112;
    const int mb = blockIdx.y;        // 0..1
    const int b  = blockIdx.z;

    const __half* __restrict__ Afrag = g_wh + (size_t)(b * 16 + mb * 8) * (16 * 32 * 8);
    const __half* __restrict__ Bg = g_xh + (size_t)b * CIN * HW;

    // B cp.async mapping: 896 16B units (64 rows x 14)
    const int kr0 = tid / 14, nc0 = tid % 14;
    const int kr1 = (tid + 256) / 14, nc1 = (tid + 256) % 14;
    const int kr2 = (tid + 512) / 14, nc2 = (tid + 512) % 14;
    const int kr3 = (tid + 768) / 14, nc3 = (tid + 768) % 14;   // tid < 128

    float4 acc[2][7];
    #pragma unroll
    for (int i = 0; i < 2; i++)
        #pragma unroll
        for (int j = 0; j < 7; j++)
            acc[i][j] = make_float4(0.f, 0.f, 0.f, 0.f);

    auto issue = [&](int c, int s) {
        const unsigned abase = sbase + (unsigned)(s * STG_BYTES);
        const unsigned bbase = abase + A_BYTES;
        // A: 1024 units; 4 per thread.  unit u: mt=u>>7, ks=(u>>5)&3, l=u&31
        #pragma unroll
        for (int i = 0; i < 4; i++) {
            const int u = tid * 4 + i;
            const int mt = u >> 7, ks = (u >> 5) & 3, l = u & 31;
            cp_async16(abase + (unsigned)u * 16,
                       Afrag + ((size_t)(mt * 16 + 4 * c + ks) * 32 + l) * 8);
        }
        const int k0 = c * BK;
        cp_async16(bbase + (unsigned)(kr0 * 240 + nc0 * 16),
                   Bg + (size_t)(k0 + kr0) * HW + n0 + nc0 * 8);
        cp_async16(bbase + (unsigned)(kr1 * 240 + nc1 * 16),
                   Bg + (size_t)(k0 + kr1) * HW + n0 + nc1 * 8);
        cp_async16(bbase + (unsigned)(kr2 * 240 + nc2 * 16),
                   Bg + (size_t)(k0 + kr2) * HW + n0 + nc2 * 8);
        if (tid < 128)
            cp_async16(bbase + (unsigned)(kr3 * 240 + nc3 * 16),
                       Bg + (size_t)(k0 + kr3) * HW + n0 + nc3 * 8);
    };

    // ---- prologue: 2 chunks in flight ----
    issue(0, 0); CP_COMMIT();
    issue(1, 1); CP_COMMIT();

    // ldmatrix addressing:
    //  x4: lanes 0-15 -> k rows at col n, lanes 16-31 -> same rows at col n+8
    const unsigned bRow4 = (unsigned)((lane & 15) * 240 + wn * 112 + (lane >> 4) * 16);
    const unsigned bRow2 = (unsigned)((lane & 15) * 240 + wn * 112);

    for (int c = 0; c < NCHUNKS; c++) {
        if (c < NCHUNKS - 1) CP_WAIT1(); else CP_WAIT0();
        __syncthreads();

        if (c + 2 < NCHUNKS) { issue(c + 2, (c + 2) % NSTAGES); CP_COMMIT(); }

        const unsigned aS = sbase + (unsigned)((c % NSTAGES) * STG_BYTES);
        const unsigned bS = aS + A_BYTES;

        #pragma unroll
        for (int ks = 0; ks < 4; ks++) {
            unsigned a0[4], a1[4];
            lds128(a0, aS + (unsigned)((((wm * 2 + 0) * 4 + ks) * 32 + lane) * 16));
            lds128(a1, aS + (unsigned)((((wm * 2 + 1) * 4 + ks) * 32 + lane) * 16));
            const unsigned bk = bS + (unsigned)(ks * 3840);
            #pragma unroll
            for (int p = 0; p < 3; p++) {
                unsigned b0, b1, b2, b3;
                ldmx4t(b0, b1, b2, b3, bk + bRow4 + (unsigned)(p * 32));
                mma16(acc[0][2 * p],     a0, b0, b1);
                mma16(acc[1][2 * p],     a1, b0, b1);
                mma16(acc[0][2 * p + 1], a0, b2, b3);
                mma16(acc[1][2 * p + 1], a1, b2, b3);
            }
            {
                unsigned b0, b1;
                ldmx2t(b0, b1, bk + bRow2 + 96u);
                mma16(acc[0][6], a0, b0, b1);
                mma16(acc[1][6], a1, b0, b1);
            }
        }
    }

    // ---- epilogue ----
    const int rr = lane >> 2;
    const int t2 = (lane & 3) * 2;
    float* __restrict__ C = out + (size_t)b * COUT * HW
                          + (size_t)(mb * BM + wm * 32) * HW + n0 + wn * 56;
    #pragma unroll
    for (int it = 0; it < 2; it++)
        #pragma unroll
        for (int nt = 0; nt < 7; nt++) {
            float* p0 = C + (size_t)(it * 16 + rr) * HW + nt * 8 + t2;
            __stcs((float2*)p0, make_float2(acc[it][nt].x, acc[it][nt].y));
            __stcs((float2*)(p0 + 8 * HW), make_float2(acc[it][nt].z, acc[it][nt].w));
        }
}

// ---------------------------------------------------------------------------
// Launch
// ---------------------------------------------------------------------------
extern "C" void kernel_launch(void* const* d_in, const int* in_sizes, int n_in,
                              void* d_out, int out_size) {
    const float* x       = (const float*)d_in[0];
    const float* weights = (const float*)d_in[1];
    const float* w1      = (const float*)d_in[2];
    const float* b1      = (const float*)d_in[3];
    const float* w2      = (const float*)d_in[4];
    const float* b2      = (const float*)d_in[5];
    float* out = (float*)d_out;

    pool_kernel<<<BATCH * CIN, 256>>>(x);
    attn_wdyn_kernel<<<dim3(16, 8), 512>>>(w1, b1, w2, b2, weights);

    cudaFuncSetAttribute(gemm_mma, cudaFuncAttributeMaxDynamicSharedMemorySize, SM_BYTES);
    dim3 grid(HW / 112, COUT / BM, BATCH);   // 28 x 2 x 32
    gemm_mma<<<grid, 256, SM_BYTES>>>(out);
}